// round 1
// baseline (speedup 1.0000x reference)
#include <cuda_runtime.h>
#include <cstdint>

#define EPSV 1e-5f

// ---------------- scratch (device globals; no allocations allowed) ----------
__device__ float g_mid[3 * 4 * 8 * 512 * 512];   // conv1 outputs (reused for final proj)
__device__ float g_qkv[3 * 4 * 512 * 512];       // Q, K, V  each (4,512,512)
__device__ float g_ctx[4 * 512 * 512];           // attention context

// ---------------- conv1: 1 -> 8 channels, 3x3 SAME, BN+ReLU folded ---------
__global__ void __launch_bounds__(256)
conv1_kernel(const float* __restrict__ xin, const float* __restrict__ w1,
             const float* __restrict__ b1, const float* __restrict__ g1,
             const float* __restrict__ be1, const float* __restrict__ m1,
             const float* __restrict__ v1, float* __restrict__ mid, int pbase)
{
    int z = blockIdx.z;
    int c = z & 7, b = (z >> 3) & 3, pl = z >> 5;
    int p = pbase + pl;
    int x = blockIdx.x * 64 + threadIdx.x;   // blockDim = (64,4)
    int y = blockIdx.y * 4 + threadIdx.y;
    int pc = p * 8 + c;
    float a  = g1[pc] * rsqrtf(v1[pc] + EPSV);
    float bb = be1[pc] + a * (b1[pc] - m1[pc]);
    const float* w  = w1 + pc * 9;
    const float* xb = xin + b * 262144;
    float s = 0.f;
    #pragma unroll
    for (int ky = 0; ky < 3; ky++) {
        int yy = y + ky - 1;
        if (yy < 0 || yy > 511) continue;
        const float* row = xb + yy * 512;
        #pragma unroll
        for (int kx = 0; kx < 3; kx++) {
            int xx = x + kx - 1;
            if (xx < 0 || xx > 511) continue;
            s += row[xx] * w[ky * 3 + kx];
        }
    }
    mid[(size_t)((pl * 4 + b) * 8 + c) * 262144 + y * 512 + x] = fmaxf(fmaf(a, s, bb), 0.f);
}

// ---------------- conv2: 8 -> 1 channel, 3x3 SAME, BN+ReLU folded ----------
__global__ void __launch_bounds__(256)
conv2_kernel(const float* __restrict__ mid, const float* __restrict__ w2,
             const float* __restrict__ b2, const float* __restrict__ g2,
             const float* __restrict__ be2, const float* __restrict__ m2,
             const float* __restrict__ v2, float* __restrict__ out, int pbase)
{
    __shared__ float tile[8][10][34];
    __shared__ float ws[72];
    int z = blockIdx.z;
    int b = z & 3, pl = z >> 2, p = pbase + pl;
    int tid = threadIdx.y * 32 + threadIdx.x;   // blockDim = (32,8)
    if (tid < 72) ws[tid] = w2[p * 72 + tid];
    float a  = g2[p] * rsqrtf(v2[p] + EPSV);
    float bb = be2[p] + a * (b2[p] - m2[p]);
    int x0 = blockIdx.x * 32, y0 = blockIdx.y * 8;
    const float* in = mid + (size_t)(pl * 4 + b) * 8 * 262144;
    for (int idx = tid; idx < 8 * 10 * 34; idx += 256) {
        int c = idx / 340, r = idx % 340, yy = r / 34, xx = r % 34;
        int gy = y0 + yy - 1, gx = x0 + xx - 1;
        float vv = 0.f;
        if (gy >= 0 && gy < 512 && gx >= 0 && gx < 512)
            vv = in[(size_t)c * 262144 + gy * 512 + gx];
        tile[c][yy][xx] = vv;
    }
    __syncthreads();
    int tx = threadIdx.x, ty = threadIdx.y;
    float s = 0.f;
    #pragma unroll
    for (int c = 0; c < 8; c++)
        #pragma unroll
        for (int ky = 0; ky < 3; ky++)
            #pragma unroll
            for (int kx = 0; kx < 3; kx++)
                s = fmaf(tile[c][ty + ky][tx + kx], ws[c * 9 + ky * 3 + kx], s);
    out[(size_t)(pl * 4 + b) * 262144 + (y0 + ty) * 512 + x0 + tx] = fmaxf(fmaf(a, s, bb), 0.f);
}

// ---------------- fused cross-head attention -------------------------------
// block = (b, i, 32-row m-tile). For each j: S = Q_tile @ K[b,j]^T / 8,
// row softmax -> write attn to gmem + keep normalized P in smem,
// ctx += P @ V[b,j]. attn never re-read from HBM.
__global__ void __launch_bounds__(256, 1)
attn_kernel(const float* __restrict__ Q, const float* __restrict__ K,
            const float* __restrict__ V, float* __restrict__ attn_out,
            float* __restrict__ ctx)
{
    extern __shared__ float smx[];
    float* Ss  = smx;                  // [32][512]
    float* KsT = smx + 32 * 512;       // [64][512] transposed K slice, XOR-swizzled cols
    float* QsT = KsT + 64 * 512;       // [64][36]  transposed Q tile (pad 4)
    float* Vs  = QsT + 64 * 36;        // [64][68]  V chunk (pad 4)

    const int tid = threadIdx.x;
    const int b = blockIdx.z, i = blockIdx.y;
    const int m0 = blockIdx.x * 32;

    const float* Qb = Q + ((size_t)b * 512 + m0) * 512 + i * 64;
    for (int idx = tid; idx < 32 * 64; idx += 256) {
        int r = idx >> 6, k = idx & 63;
        QsT[k * 36 + r] = Qb[r * 512 + k];
    }

    const int rg = tid >> 6;    // row group: rows 8*rg .. 8*rg+7
    const int cg = tid & 63;    // col group: cols 8*cg .. 8*cg+7 (S) / col cg (ctx)
    float cacc[8];
    #pragma unroll
    for (int u = 0; u < 8; u++) cacc[u] = 0.f;

    for (int j = 0; j < 8; j++) {
        __syncthreads();
        // load K[b, :, j*64 .. +63] transposed into KsT[k][n], swizzled
        const float* Kb = K + (size_t)b * 262144 + j * 64;
        for (int idx = tid; idx < 512 * 64; idx += 256) {
            int n = idx >> 6, k = idx & 63;
            KsT[k * 512 + (n ^ ((k & 7) << 2))] = Kb[(size_t)n * 512 + k];
        }
        __syncthreads();

        // S tile 32x512, 8x8 micro-tile per thread
        float acc[8][8];
        #pragma unroll
        for (int ri = 0; ri < 8; ri++)
            #pragma unroll
            for (int ci = 0; ci < 8; ci++) acc[ri][ci] = 0.f;

        #pragma unroll 8
        for (int k = 0; k < 64; k++) {
            float4 q0 = *(const float4*)&QsT[k * 36 + 8 * rg];
            float4 q1 = *(const float4*)&QsT[k * 36 + 8 * rg + 4];
            int swz = (k & 7) << 2;
            float4 k0 = *(const float4*)&KsT[k * 512 + ((8 * cg) ^ swz)];
            float4 k1 = *(const float4*)&KsT[k * 512 + ((8 * cg + 4) ^ swz)];
            float qv[8] = {q0.x, q0.y, q0.z, q0.w, q1.x, q1.y, q1.z, q1.w};
            float kv[8] = {k0.x, k0.y, k0.z, k0.w, k1.x, k1.y, k1.z, k1.w};
            #pragma unroll
            for (int ri = 0; ri < 8; ri++)
                #pragma unroll
                for (int ci = 0; ci < 8; ci++)
                    acc[ri][ci] = fmaf(qv[ri], kv[ci], acc[ri][ci]);
        }
        #pragma unroll
        for (int ri = 0; ri < 8; ri++) {
            float4 s0, s1;
            s0.x = acc[ri][0] * 0.125f; s0.y = acc[ri][1] * 0.125f;
            s0.z = acc[ri][2] * 0.125f; s0.w = acc[ri][3] * 0.125f;
            s1.x = acc[ri][4] * 0.125f; s1.y = acc[ri][5] * 0.125f;
            s1.z = acc[ri][6] * 0.125f; s1.w = acc[ri][7] * 0.125f;
            *(float4*)&Ss[(8 * rg + ri) * 512 + 8 * cg]     = s0;
            *(float4*)&Ss[(8 * rg + ri) * 512 + 8 * cg + 4] = s1;
        }
        __syncthreads();

        // row softmax (axis n), write normalized P to smem + gmem attn
        int w = tid >> 5, lane = tid & 31;
        float* ab = attn_out + ((((size_t)b * 8 + i) * 8 + j) * 512 + m0) * 512;
        for (int r = 4 * w; r < 4 * w + 4; r++) {
            float vals[16];
            float mx = -3.4e38f;
            #pragma unroll
            for (int t = 0; t < 16; t++) {
                vals[t] = Ss[r * 512 + lane + 32 * t];
                mx = fmaxf(mx, vals[t]);
            }
            #pragma unroll
            for (int o = 16; o > 0; o >>= 1) mx = fmaxf(mx, __shfl_xor_sync(0xffffffffu, mx, o));
            float sum = 0.f;
            #pragma unroll
            for (int t = 0; t < 16; t++) { vals[t] = __expf(vals[t] - mx); sum += vals[t]; }
            #pragma unroll
            for (int o = 16; o > 0; o >>= 1) sum += __shfl_xor_sync(0xffffffffu, sum, o);
            float inv = 1.f / sum;
            #pragma unroll
            for (int t = 0; t < 16; t++) {
                float pv = vals[t] * inv;
                Ss[r * 512 + lane + 32 * t] = pv;
                ab[(size_t)r * 512 + lane + 32 * t] = pv;
            }
        }
        __syncthreads();

        // ctx += P(32x512) @ V[b,j](512x64), chunked over n
        for (int nc = 0; nc < 8; nc++) {
            const float* Vb = V + ((size_t)b * 512 + nc * 64) * 512 + j * 64;
            for (int idx = tid; idx < 64 * 64; idx += 256) {
                int n = idx >> 6, c2 = idx & 63;
                Vs[n * 68 + c2] = Vb[(size_t)n * 512 + c2];
            }
            __syncthreads();
            #pragma unroll 8
            for (int n = 0; n < 64; n++) {
                float vv = Vs[n * 68 + cg];
                #pragma unroll
                for (int ri = 0; ri < 8; ri++)
                    cacc[ri] = fmaf(Ss[(8 * rg + ri) * 512 + nc * 64 + n], vv, cacc[ri]);
            }
            __syncthreads();
        }
    }
    #pragma unroll
    for (int ri = 0; ri < 8; ri++)
        ctx[((size_t)b * 512 + m0 + 8 * rg + ri) * 512 + i * 64 + cg] = cacc[ri];
}

// ---------------- launch ----------------------------------------------------
extern "C" void kernel_launch(void* const* d_in, const int* in_sizes, int n_in,
                              void* d_out, int out_size)
{
    const float* X   = (const float*)d_in[0];
    // d_in[1] = valid_lens : unused by the reference
    const float* w1  = (const float*)d_in[2];
    const float* b1  = (const float*)d_in[3];
    const float* g1  = (const float*)d_in[4];
    const float* be1 = (const float*)d_in[5];
    const float* m1  = (const float*)d_in[6];
    const float* v1  = (const float*)d_in[7];
    const float* w2  = (const float*)d_in[8];
    const float* b2  = (const float*)d_in[9];
    const float* g2  = (const float*)d_in[10];
    const float* be2 = (const float*)d_in[11];
    const float* m2  = (const float*)d_in[12];
    const float* v2  = (const float*)d_in[13];

    float* out  = (float*)d_out;                       // (4,512,512)
    float* attn = out + (size_t)4 * 512 * 512;         // (4,8,8,512,512)

    float *mid, *qkv, *ctx;
    cudaGetSymbolAddress((void**)&mid, g_mid);
    cudaGetSymbolAddress((void**)&qkv, g_qkv);
    cudaGetSymbolAddress((void**)&ctx, g_ctx);

    const int SMEM = (32 * 512 + 64 * 512 + 64 * 36 + 64 * 68) * 4;  // 223232 B
    cudaFuncSetAttribute(attn_kernel, cudaFuncAttributeMaxDynamicSharedMemorySize, SMEM);

    dim3 cb1(64, 4), cb2(32, 8);

    // Q,K,V projections
    conv1_kernel<<<dim3(8, 128, 96), cb1>>>(X, w1, b1, g1, be1, m1, v1, mid, 0);
    conv2_kernel<<<dim3(16, 64, 12), cb2>>>(mid, w2, b2, g2, be2, m2, v2, qkv, 0);

    // fused cross-head attention: writes attn output + ctx
    attn_kernel<<<dim3(16, 8, 4), 256, SMEM>>>(qkv, qkv + 1048576, qkv + 2097152, attn, ctx);

    // output projection
    conv1_kernel<<<dim3(8, 128, 32), cb1>>>(ctx, w1, b1, g1, be1, m1, v1, mid, 3);
    conv2_kernel<<<dim3(16, 64, 4), cb2>>>(mid, w2, b2, g2, be2, m2, v2, out, 3);
}

// round 2
// speedup vs baseline: 1.5240x; 1.5240x over previous
#include <cuda_runtime.h>
#include <cstdint>

#define EPSV 1e-5f

// ---------------- scratch (device globals; no allocations allowed) ----------
__device__ float g_mid[3 * 4 * 8 * 512 * 512];
__device__ float g_qkv[3 * 4 * 512 * 512];
__device__ float g_ctx[4 * 512 * 512];

// ---------------- f32x2 helpers ---------------------------------------------
__device__ __forceinline__ unsigned long long pk2(float lo, float hi) {
    unsigned long long r;
    asm("mov.b64 %0, {%1, %2};" : "=l"(r) : "f"(lo), "f"(hi));
    return r;
}
__device__ __forceinline__ unsigned long long fma2(unsigned long long a,
                                                   unsigned long long b,
                                                   unsigned long long c) {
    unsigned long long d;
    asm("fma.rn.f32x2 %0, %1, %2, %3;" : "=l"(d) : "l"(a), "l"(b), "l"(c));
    return d;
}
union U2 { unsigned long long u[2]; float4 v; float f[4]; };

// ---------------- conv1: 1 -> 8 channels, 3x3 SAME, BN+ReLU folded ---------
__global__ void __launch_bounds__(256)
conv1_kernel(const float* __restrict__ xin, const float* __restrict__ w1,
             const float* __restrict__ b1, const float* __restrict__ g1,
             const float* __restrict__ be1, const float* __restrict__ m1,
             const float* __restrict__ v1, float* __restrict__ mid, int pbase)
{
    int z = blockIdx.z;
    int c = z & 7, b = (z >> 3) & 3, pl = z >> 5;
    int p = pbase + pl;
    int x = blockIdx.x * 64 + threadIdx.x;
    int y = blockIdx.y * 4 + threadIdx.y;
    int pc = p * 8 + c;
    float a  = g1[pc] * rsqrtf(v1[pc] + EPSV);
    float bb = be1[pc] + a * (b1[pc] - m1[pc]);
    const float* w  = w1 + pc * 9;
    const float* xb = xin + b * 262144;
    float s = 0.f;
    #pragma unroll
    for (int ky = 0; ky < 3; ky++) {
        int yy = y + ky - 1;
        if (yy < 0 || yy > 511) continue;
        const float* row = xb + yy * 512;
        #pragma unroll
        for (int kx = 0; kx < 3; kx++) {
            int xx = x + kx - 1;
            if (xx < 0 || xx > 511) continue;
            s += row[xx] * w[ky * 3 + kx];
        }
    }
    mid[(size_t)((pl * 4 + b) * 8 + c) * 262144 + y * 512 + x] = fmaxf(fmaf(a, s, bb), 0.f);
}

// ---------------- conv2: 8 -> 1 channel, 3x3 SAME, BN+ReLU folded ----------
__global__ void __launch_bounds__(256)
conv2_kernel(const float* __restrict__ mid, const float* __restrict__ w2,
             const float* __restrict__ b2, const float* __restrict__ g2,
             const float* __restrict__ be2, const float* __restrict__ m2,
             const float* __restrict__ v2, float* __restrict__ out, int pbase)
{
    __shared__ float tile[8][10][34];
    __shared__ float ws[72];
    int z = blockIdx.z;
    int b = z & 3, pl = z >> 2, p = pbase + pl;
    int tid = threadIdx.y * 32 + threadIdx.x;
    if (tid < 72) ws[tid] = w2[p * 72 + tid];
    float a  = g2[p] * rsqrtf(v2[p] + EPSV);
    float bb = be2[p] + a * (b2[p] - m2[p]);
    int x0 = blockIdx.x * 32, y0 = blockIdx.y * 8;
    const float* in = mid + (size_t)(pl * 4 + b) * 8 * 262144;
    for (int idx = tid; idx < 8 * 10 * 34; idx += 256) {
        int c = idx / 340, r = idx % 340, yy = r / 34, xx = r % 34;
        int gy = y0 + yy - 1, gx = x0 + xx - 1;
        float vv = 0.f;
        if (gy >= 0 && gy < 512 && gx >= 0 && gx < 512)
            vv = in[(size_t)c * 262144 + gy * 512 + gx];
        tile[c][yy][xx] = vv;
    }
    __syncthreads();
    int tx = threadIdx.x, ty = threadIdx.y;
    float s = 0.f;
    #pragma unroll
    for (int c = 0; c < 8; c++)
        #pragma unroll
        for (int ky = 0; ky < 3; ky++)
            #pragma unroll
            for (int kx = 0; kx < 3; kx++)
                s = fmaf(tile[c][ty + ky][tx + kx], ws[c * 9 + ky * 3 + kx], s);
    out[(size_t)(pl * 4 + b) * 262144 + (y0 + ty) * 512 + x0 + tx] = fmaxf(fmaf(a, s, bb), 0.f);
}

// ---------------- fused cross-head attention, v2 ----------------------------
// 256 threads, 115200 B smem -> 2 CTAs/SM. f32x2 FFMA in both GEMM phases.
// smem layout (floats):
//   Ss  [32][516]          S / P tile               (16512)
//   KsT [8][512]           K^T k-chunk, swizzled    ( 4096)
//   QsT [64][32]           Q^T, swizzled, prescaled ( 2048)
//   Vs  [32][64]           V chunk (split n-halves) ( 2048)
//   Cs  [2][32][64]        ctx accumulators         ( 4096)
#define SS_STRIDE 516
#define OFF_KST  16512
#define OFF_QST  20608
#define OFF_VS   22656
#define OFF_CS   24704
#define SMEM_WORDS 28800

__global__ void __launch_bounds__(256, 2)
attn_kernel(const float* __restrict__ Q, const float* __restrict__ K,
            const float* __restrict__ V, float* __restrict__ attn_out,
            float* __restrict__ ctx)
{
    extern __shared__ float sm[];
    float* Ss  = sm;
    float* KsT = sm + OFF_KST;
    float* QsT = sm + OFF_QST;
    float* Vs  = sm + OFF_VS;
    float* Cs  = sm + OFF_CS;

    const int tid = threadIdx.x;
    const int b = blockIdx.z, i = blockIdx.y;
    const int m0 = blockIdx.x * 32;

    // zero ctx accumulators
    for (int idx = tid; idx < 4096; idx += 256) Cs[idx] = 0.f;

    // load Q tile transposed + swizzled, pre-scaled by 1/sqrt(64)
    const float* Qb = Q + ((size_t)b * 512 + m0) * 512 + i * 64;
    for (int t = 0; t < 8; t++) {
        int idx = tid + t * 256;
        int r = idx >> 6, k = idx & 63;
        QsT[k * 32 + (r ^ ((k & 7) << 2))] = Qb[r * 512 + k] * 0.125f;
    }

    // S-gemm thread mapping: rows 8*rg..+7, cols 8*cg..+7
    const int rg = tid >> 6;
    const int cg = tid & 63;
    // ctx thread mapping: n-half, 4 rows x 4 cols
    const int half = tid >> 7;
    const int slot = tid & 127;
    const int crg  = slot >> 4;          // rows 4*crg..+3
    const int ccol = (slot & 15) * 4;    // cols ccol..+3

    const float* Kbase = K + (size_t)b * 262144;
    const float* Vbase = V + (size_t)b * 262144;

    for (int j = 0; j < 8; j++) {
        // ---------- S = Q K^T (pre-scaled), k-chunked ----------
        unsigned long long acc2[8][4];
        #pragma unroll
        for (int ri = 0; ri < 8; ri++)
            #pragma unroll
            for (int cp = 0; cp < 4; cp++) acc2[ri][cp] = 0ull;

        const float* Kb = Kbase + j * 64;
        for (int kc = 0; kc < 8; kc++) {
            __syncthreads();
            // load K chunk [8 k][512 n] transposed, conflict-free swizzled store
            {
                int kk = tid & 7;
                int n0 = tid >> 3;                 // 0..31
                int ka = kc * 8 + kk;
                #pragma unroll
                for (int t = 0; t < 16; t++) {
                    int n = n0 + t * 32;
                    KsT[kk * 512 + (n ^ (kk << 2))] = Kb[(size_t)n * 512 + ka];
                }
            }
            __syncthreads();
            #pragma unroll
            for (int k = 0; k < 8; k++) {
                int swz = k << 2;
                U2 q0, q1, k0, k1;
                q0.v = *(const float4*)&QsT[(kc * 8 + k) * 32 + ((8 * rg) ^ swz)];
                q1.v = *(const float4*)&QsT[(kc * 8 + k) * 32 + ((8 * rg + 4) ^ swz)];
                k0.v = *(const float4*)&KsT[k * 512 + ((8 * cg) ^ swz)];
                k1.v = *(const float4*)&KsT[k * 512 + ((8 * cg + 4) ^ swz)];
                unsigned long long kv[4] = { k0.u[0], k0.u[1], k1.u[0], k1.u[1] };
                float qs[8] = { q0.f[0], q0.f[1], q0.f[2], q0.f[3],
                                q1.f[0], q1.f[1], q1.f[2], q1.f[3] };
                #pragma unroll
                for (int ri = 0; ri < 8; ri++) {
                    unsigned long long qp = pk2(qs[ri], qs[ri]);
                    #pragma unroll
                    for (int cp = 0; cp < 4; cp++)
                        acc2[ri][cp] = fma2(qp, kv[cp], acc2[ri][cp]);
                }
            }
        }
        // store S tile (vector stores; pairs are consecutive columns)
        #pragma unroll
        for (int ri = 0; ri < 8; ri++) {
            U2 s0, s1;
            s0.u[0] = acc2[ri][0]; s0.u[1] = acc2[ri][1];
            s1.u[0] = acc2[ri][2]; s1.u[1] = acc2[ri][3];
            *(float4*)&Ss[(8 * rg + ri) * SS_STRIDE + 8 * cg]     = s0.v;
            *(float4*)&Ss[(8 * rg + ri) * SS_STRIDE + 8 * cg + 4] = s1.v;
        }
        __syncthreads();

        // ---------- row softmax, write attn (streaming) ----------
        {
            int w = tid >> 5, lane = tid & 31;
            float* ab = attn_out + ((((size_t)b * 8 + i) * 8 + j) * 512 + m0) * 512;
            for (int r = 4 * w; r < 4 * w + 4; r++) {
                float vals[16];
                float mx = -3.4e38f;
                #pragma unroll
                for (int t = 0; t < 16; t++) {
                    vals[t] = Ss[r * SS_STRIDE + lane + 32 * t];
                    mx = fmaxf(mx, vals[t]);
                }
                #pragma unroll
                for (int o = 16; o > 0; o >>= 1) mx = fmaxf(mx, __shfl_xor_sync(0xffffffffu, mx, o));
                float sum = 0.f;
                #pragma unroll
                for (int t = 0; t < 16; t++) { vals[t] = __expf(vals[t] - mx); sum += vals[t]; }
                #pragma unroll
                for (int o = 16; o > 0; o >>= 1) sum += __shfl_xor_sync(0xffffffffu, sum, o);
                float inv = 1.f / sum;
                #pragma unroll
                for (int t = 0; t < 16; t++) {
                    float pv = vals[t] * inv;
                    Ss[r * SS_STRIDE + lane + 32 * t] = pv;
                    __stcs(&ab[(size_t)r * 512 + lane + 32 * t], pv);
                }
            }
        }

        // ---------- ctx += P @ V, n split in halves, f32x2 over n-pairs ------
        unsigned long long cacc[4][4];
        #pragma unroll
        for (int r = 0; r < 4; r++)
            #pragma unroll
            for (int c = 0; c < 4; c++) cacc[r][c] = 0ull;

        const float* Vb = Vbase + j * 64;
        for (int vc = 0; vc < 16; vc++) {
            __syncthreads();
            // load 32 V rows: [0..15] -> n = vc*16.., [16..31] -> n = 256+vc*16..
            {
                #pragma unroll
                for (int t = 0; t < 8; t++) {
                    int idx = tid + t * 256;
                    int lr = idx >> 6, col = idx & 63;
                    int n = (lr < 16) ? (vc * 16 + lr) : (256 + vc * 16 + lr - 16);
                    Vs[lr * 64 + col] = Vb[(size_t)n * 512 + col];
                }
            }
            __syncthreads();
            int nb = half * 256 + vc * 16;
            #pragma unroll
            for (int np = 0; np < 8; np++) {
                int lb = half * 16 + np * 2;
                int n  = nb + np * 2;
                U2 v0, v1;
                v0.v = *(const float4*)&Vs[lb * 64 + ccol];
                v1.v = *(const float4*)&Vs[(lb + 1) * 64 + ccol];
                unsigned long long vp[4] = {
                    pk2(v0.f[0], v1.f[0]), pk2(v0.f[1], v1.f[1]),
                    pk2(v0.f[2], v1.f[2]), pk2(v0.f[3], v1.f[3]) };
                #pragma unroll
                for (int r = 0; r < 4; r++) {
                    unsigned long long pp =
                        *(const unsigned long long*)&Ss[(4 * crg + r) * SS_STRIDE + n];
                    #pragma unroll
                    for (int c = 0; c < 4; c++)
                        cacc[r][c] = fma2(pp, vp[c], cacc[r][c]);
                }
            }
        }
        // fold per-j partials into smem ctx accumulators (exclusive cells)
        #pragma unroll
        for (int r = 0; r < 4; r++)
            #pragma unroll
            for (int c = 0; c < 4; c++) {
                float2 un = *(float2*)&cacc[r][c];
                Cs[(half * 32 + 4 * crg + r) * 64 + ccol + c] += un.x + un.y;
            }
    }
    __syncthreads();
    // combine halves, write ctx
    for (int t = 0; t < 8; t++) {
        int idx = tid + t * 256;
        int r = idx >> 6, c = idx & 63;
        float vv = Cs[r * 64 + c] + Cs[2048 + r * 64 + c];
        ctx[((size_t)b * 512 + m0 + r) * 512 + i * 64 + c] = vv;
    }
}

// ---------------- launch ----------------------------------------------------
extern "C" void kernel_launch(void* const* d_in, const int* in_sizes, int n_in,
                              void* d_out, int out_size)
{
    const float* X   = (const float*)d_in[0];
    const float* w1  = (const float*)d_in[2];
    const float* b1  = (const float*)d_in[3];
    const float* g1  = (const float*)d_in[4];
    const float* be1 = (const float*)d_in[5];
    const float* m1  = (const float*)d_in[6];
    const float* v1  = (const float*)d_in[7];
    const float* w2  = (const float*)d_in[8];
    const float* b2  = (const float*)d_in[9];
    const float* g2  = (const float*)d_in[10];
    const float* be2 = (const float*)d_in[11];
    const float* m2  = (const float*)d_in[12];
    const float* v2  = (const float*)d_in[13];

    float* out  = (float*)d_out;
    float* attn = out + (size_t)4 * 512 * 512;

    float *mid, *qkv, *ctx;
    cudaGetSymbolAddress((void**)&mid, g_mid);
    cudaGetSymbolAddress((void**)&qkv, g_qkv);
    cudaGetSymbolAddress((void**)&ctx, g_ctx);

    const int SMEM = SMEM_WORDS * 4;  // 115200 B
    cudaFuncSetAttribute(attn_kernel, cudaFuncAttributeMaxDynamicSharedMemorySize, SMEM);

    dim3 cb1(64, 4), cb2(32, 8);

    conv1_kernel<<<dim3(8, 128, 96), cb1>>>(X, w1, b1, g1, be1, m1, v1, mid, 0);
    conv2_kernel<<<dim3(16, 64, 12), cb2>>>(mid, w2, b2, g2, be2, m2, v2, qkv, 0);

    attn_kernel<<<dim3(16, 8, 4), 256, SMEM>>>(qkv, qkv + 1048576, qkv + 2097152, attn, ctx);

    conv1_kernel<<<dim3(8, 128, 32), cb1>>>(ctx, w1, b1, g1, be1, m1, v1, mid, 3);
    conv2_kernel<<<dim3(16, 64, 4), cb2>>>(mid, w2, b2, g2, be2, m2, v2, out, 3);
}

// round 3
// speedup vs baseline: 1.8927x; 1.2420x over previous
#include <cuda_runtime.h>
#include <cstdint>

#define EPSV 1e-5f

// ---------------- scratch (device globals; no allocations allowed) ----------
__device__ float g_mid[3 * 4 * 8 * 512 * 512];
__device__ float g_qkv[3 * 4 * 512 * 512];
__device__ float g_ctx[4 * 512 * 512];

// ---------------- f32x2 helpers ---------------------------------------------
__device__ __forceinline__ unsigned long long pk2(float lo, float hi) {
    unsigned long long r;
    asm("mov.b64 %0, {%1, %2};" : "=l"(r) : "f"(lo), "f"(hi));
    return r;
}
__device__ __forceinline__ unsigned long long fma2(unsigned long long a,
                                                   unsigned long long b,
                                                   unsigned long long c) {
    unsigned long long d;
    asm("fma.rn.f32x2 %0, %1, %2, %3;" : "=l"(d) : "l"(a), "l"(b), "l"(c));
    return d;
}
union U2 { unsigned long long u[2]; float4 v; float f[4]; };

// ---------------- conv1: 1 -> 8 channels, 3x3 SAME, BN+ReLU folded ---------
__global__ void __launch_bounds__(256)
conv1_kernel(const float* __restrict__ xin, const float* __restrict__ w1,
             const float* __restrict__ b1, const float* __restrict__ g1,
             const float* __restrict__ be1, const float* __restrict__ m1,
             const float* __restrict__ v1, float* __restrict__ mid, int pbase)
{
    int z = blockIdx.z;
    int c = z & 7, b = (z >> 3) & 3, pl = z >> 5;
    int p = pbase + pl;
    int x = blockIdx.x * 64 + threadIdx.x;
    int y = blockIdx.y * 4 + threadIdx.y;
    int pc = p * 8 + c;
    float a  = g1[pc] * rsqrtf(v1[pc] + EPSV);
    float bb = be1[pc] + a * (b1[pc] - m1[pc]);
    const float* w  = w1 + pc * 9;
    const float* xb = xin + b * 262144;
    float s;
    if (x > 0 && x < 511 && y > 0 && y < 511) {
        const float* r0 = xb + (y - 1) * 512 + x;
        const float* r1 = r0 + 512;
        const float* r2 = r1 + 512;
        s = r0[-1] * w[0] + r0[0] * w[1] + r0[1] * w[2]
          + r1[-1] * w[3] + r1[0] * w[4] + r1[1] * w[5]
          + r2[-1] * w[6] + r2[0] * w[7] + r2[1] * w[8];
    } else {
        s = 0.f;
        #pragma unroll
        for (int ky = 0; ky < 3; ky++) {
            int yy = y + ky - 1;
            if (yy < 0 || yy > 511) continue;
            const float* row = xb + yy * 512;
            #pragma unroll
            for (int kx = 0; kx < 3; kx++) {
                int xx = x + kx - 1;
                if (xx < 0 || xx > 511) continue;
                s += row[xx] * w[ky * 3 + kx];
            }
        }
    }
    mid[(size_t)((pl * 4 + b) * 8 + c) * 262144 + y * 512 + x] = fmaxf(fmaf(a, s, bb), 0.f);
}

// ---------------- conv2: 8 -> 1 channel, 3x3 SAME, BN+ReLU folded ----------
__global__ void __launch_bounds__(256)
conv2_kernel(const float* __restrict__ mid, const float* __restrict__ w2,
             const float* __restrict__ b2, const float* __restrict__ g2,
             const float* __restrict__ be2, const float* __restrict__ m2,
             const float* __restrict__ v2, float* __restrict__ out, int pbase)
{
    __shared__ float tile[8][10][34];
    __shared__ float ws[72];
    int z = blockIdx.z;
    int b = z & 3, pl = z >> 2, p = pbase + pl;
    int tid = threadIdx.y * 32 + threadIdx.x;
    if (tid < 72) ws[tid] = w2[p * 72 + tid];
    float a  = g2[p] * rsqrtf(v2[p] + EPSV);
    float bb = be2[p] + a * (b2[p] - m2[p]);
    int x0 = blockIdx.x * 32, y0 = blockIdx.y * 8;
    const float* in = mid + (size_t)(pl * 4 + b) * 8 * 262144;
    for (int idx = tid; idx < 8 * 10 * 34; idx += 256) {
        int c = idx / 340, r = idx % 340, yy = r / 34, xx = r % 34;
        int gy = y0 + yy - 1, gx = x0 + xx - 1;
        float vv = 0.f;
        if (gy >= 0 && gy < 512 && gx >= 0 && gx < 512)
            vv = in[(size_t)c * 262144 + gy * 512 + gx];
        tile[c][yy][xx] = vv;
    }
    __syncthreads();
    int tx = threadIdx.x, ty = threadIdx.y;
    float s = 0.f;
    #pragma unroll
    for (int c = 0; c < 8; c++)
        #pragma unroll
        for (int ky = 0; ky < 3; ky++)
            #pragma unroll
            for (int kx = 0; kx < 3; kx++)
                s = fmaf(tile[c][ty + ky][tx + kx], ws[c * 9 + ky * 3 + kx], s);
    out[(size_t)(pl * 4 + b) * 262144 + (y0 + ty) * 512 + x0 + tx] = fmaxf(fmaf(a, s, bb), 0.f);
}

// ---------------- fused cross-head attention, v3 ----------------------------
// 512 threads, m-tile 64, 1 CTA/SM (216 KB smem), register-prefetch pipelined
// K/V chunk loads, split-column conflict-free LDS, f32x2 FMA throughout.
// smem (float offsets):
#define SSTR 516
#define OFF_KST 33024              // Ss [64][516]
#define OFF_QST 37152              // KsT [8][516]
#define OFF_VS  41504              // QsT [64][68]
#define OFF_CS  45856              // Vs  [64][68]
#define SMEM_WORDS 54048           // Cs  [2][64][64]

__global__ void __launch_bounds__(512, 1)
attn_kernel(const float* __restrict__ Q, const float* __restrict__ K,
            const float* __restrict__ V, float* __restrict__ attn_out,
            float* __restrict__ ctx)
{
    extern __shared__ float sm[];
    float* Ss  = sm;
    float* KsT = sm + OFF_KST;
    float* QsT = sm + OFF_QST;
    float* Vs  = sm + OFF_VS;
    float* Cs  = sm + OFF_CS;

    const int tid = threadIdx.x;
    const int b = blockIdx.z, i = blockIdx.y;
    const int m0 = blockIdx.x * 64;

    // zero ctx accumulators
    #pragma unroll
    for (int t = 0; t < 16; t++) Cs[tid + t * 512] = 0.f;

    // Q tile (64 x 64) transposed into QsT[k][row], prescaled by 1/8
    const float* Qb = Q + ((size_t)b * 512 + m0) * 512 + i * 64;
    #pragma unroll
    for (int t = 0; t < 8; t++) {
        int idx = tid + t * 512;
        int r = idx >> 6, k = idx & 63;
        QsT[k * 68 + r] = Qb[r * 512 + k] * 0.125f;
    }

    // S-gemm mapping: rows 8*rg..+7 ; cols 4*cg..+3 and 256+4*cg..+3
    const int rg = tid >> 6;
    const int cg = tid & 63;
    // ctx mapping: n-half, rows 4*crg..+3, cols ccol..+3
    const int half = tid >> 8;
    const int slot = tid & 255;
    const int crg  = slot >> 4;
    const int ccol = (slot & 15) * 4;
    // K/V staging thread roles
    const int kk = tid & 7, n0 = tid >> 3;      // K: 8 floats/thread/chunk

    const float* Kb = K + (size_t)b * 262144 + /*j*/ 0;   // rebased per j
    const float* Vbase = V + (size_t)b * 262144;

    float kreg[8], vreg[8];

    for (int j = 0; j < 8; j++) {
        const float* Kj = K + (size_t)b * 262144 + j * 64;
        const float* Vj = Vbase + j * 64;

        // prefetch K chunk 0
        #pragma unroll
        for (int t = 0; t < 8; t++) kreg[t] = Kj[(size_t)(n0 + 64 * t) * 512 + kk];

        unsigned long long acc2[8][4];
        #pragma unroll
        for (int ri = 0; ri < 8; ri++)
            #pragma unroll
            for (int cp = 0; cp < 4; cp++) acc2[ri][cp] = 0ull;

        for (int kc = 0; kc < 8; kc++) {
            __syncthreads();
            #pragma unroll
            for (int t = 0; t < 8; t++)
                KsT[kk * 516 + n0 + 64 * t] = kreg[t];
            __syncthreads();
            if (kc < 7) {
                int ka = (kc + 1) * 8 + kk;
                #pragma unroll
                for (int t = 0; t < 8; t++)
                    kreg[t] = Kj[(size_t)(n0 + 64 * t) * 512 + ka];
            }
            #pragma unroll
            for (int k = 0; k < 8; k++) {
                int kr = kc * 8 + k;
                U2 q0, q1, k0, k1;
                q0.v = *(const float4*)&QsT[kr * 68 + 8 * rg];
                q1.v = *(const float4*)&QsT[kr * 68 + 8 * rg + 4];
                k0.v = *(const float4*)&KsT[k * 516 + 4 * cg];
                k1.v = *(const float4*)&KsT[k * 516 + 256 + 4 * cg];
                unsigned long long kv[4] = { k0.u[0], k0.u[1], k1.u[0], k1.u[1] };
                float qs[8] = { q0.f[0], q0.f[1], q0.f[2], q0.f[3],
                                q1.f[0], q1.f[1], q1.f[2], q1.f[3] };
                #pragma unroll
                for (int ri = 0; ri < 8; ri++) {
                    unsigned long long qp = pk2(qs[ri], qs[ri]);
                    #pragma unroll
                    for (int cp = 0; cp < 4; cp++)
                        acc2[ri][cp] = fma2(qp, kv[cp], acc2[ri][cp]);
                }
            }
        }
        // store S: cols [4cg..+3] and [256+4cg..+3]
        #pragma unroll
        for (int ri = 0; ri < 8; ri++) {
            U2 s0, s1;
            s0.u[0] = acc2[ri][0]; s0.u[1] = acc2[ri][1];
            s1.u[0] = acc2[ri][2]; s1.u[1] = acc2[ri][3];
            *(float4*)&Ss[(8 * rg + ri) * SSTR + 4 * cg]       = s0.v;
            *(float4*)&Ss[(8 * rg + ri) * SSTR + 256 + 4 * cg] = s1.v;
        }

        // prefetch V chunk 0 (independent of softmax)
        #pragma unroll
        for (int t = 0; t < 8; t++) {
            int idx = tid + t * 512;
            int lr = idx >> 6, col = idx & 63;
            int n = (lr < 32) ? lr : (256 + lr - 32);
            vreg[t] = Vj[(size_t)n * 512 + col];
        }
        __syncthreads();

        // ---------- row softmax over n (512), write attn ----------
        {
            int w = tid >> 5, lane = tid & 31;
            float* ab = attn_out + ((((size_t)b * 8 + i) * 8 + j) * 512 + m0) * 512;
            for (int r = 4 * w; r < 4 * w + 4; r++) {
                float vals[16];
                float mx = -3.4e38f;
                #pragma unroll
                for (int t = 0; t < 16; t++) {
                    vals[t] = Ss[r * SSTR + lane + 32 * t];
                    mx = fmaxf(mx, vals[t]);
                }
                #pragma unroll
                for (int o = 16; o > 0; o >>= 1) mx = fmaxf(mx, __shfl_xor_sync(0xffffffffu, mx, o));
                float sum = 0.f;
                #pragma unroll
                for (int t = 0; t < 16; t++) { vals[t] = __expf(vals[t] - mx); sum += vals[t]; }
                #pragma unroll
                for (int o = 16; o > 0; o >>= 1) sum += __shfl_xor_sync(0xffffffffu, sum, o);
                float inv = 1.f / sum;
                #pragma unroll
                for (int t = 0; t < 16; t++) {
                    float pv = vals[t] * inv;
                    Ss[r * SSTR + lane + 32 * t] = pv;
                    __stcs(&ab[(size_t)r * 512 + lane + 32 * t], pv);
                }
            }
        }

        // ---------- ctx += P @ V (n-halves, f32x2 over n-pairs) ----------
        unsigned long long cacc[4][4];
        #pragma unroll
        for (int r = 0; r < 4; r++)
            #pragma unroll
            for (int c = 0; c < 4; c++) cacc[r][c] = 0ull;

        for (int vc = 0; vc < 8; vc++) {
            __syncthreads();   // Vs free + (vc==0) softmax done
            #pragma unroll
            for (int t = 0; t < 8; t++) {
                int idx = tid + t * 512;
                int lr = idx >> 6, col = idx & 63;
                Vs[lr * 68 + col] = vreg[t];
            }
            __syncthreads();
            if (vc < 7) {
                #pragma unroll
                for (int t = 0; t < 8; t++) {
                    int idx = tid + t * 512;
                    int lr = idx >> 6, col = idx & 63;
                    int n = (lr < 32) ? ((vc + 1) * 32 + lr)
                                      : (256 + (vc + 1) * 32 + lr - 32);
                    vreg[t] = Vj[(size_t)n * 512 + col];
                }
            }
            int nbase = half * 256 + vc * 32;
            #pragma unroll
            for (int np = 0; np < 16; np++) {
                int lb = half * 32 + np * 2;
                U2 v0, v1;
                v0.v = *(const float4*)&Vs[lb * 68 + ccol];
                v1.v = *(const float4*)&Vs[(lb + 1) * 68 + ccol];
                unsigned long long vp[4] = {
                    pk2(v0.f[0], v1.f[0]), pk2(v0.f[1], v1.f[1]),
                    pk2(v0.f[2], v1.f[2]), pk2(v0.f[3], v1.f[3]) };
                int n = nbase + np * 2;
                #pragma unroll
                for (int r = 0; r < 4; r++) {
                    unsigned long long pp =
                        *(const unsigned long long*)&Ss[(4 * crg + r) * SSTR + n];
                    #pragma unroll
                    for (int c = 0; c < 4; c++)
                        cacc[r][c] = fma2(pp, vp[c], cacc[r][c]);
                }
            }
        }
        // fold per-j partials (exclusive cells)
        #pragma unroll
        for (int r = 0; r < 4; r++)
            #pragma unroll
            for (int c = 0; c < 4; c++) {
                float2 un = *(float2*)&cacc[r][c];
                Cs[(size_t)half * 4096 + (4 * crg + r) * 64 + ccol + c] += un.x + un.y;
            }
    }
    __syncthreads();
    // combine halves, write ctx
    #pragma unroll
    for (int t = 0; t < 8; t++) {
        int idx = tid + t * 512;
        int r = idx >> 6, c = idx & 63;
        float vv = Cs[r * 64 + c] + Cs[4096 + r * 64 + c];
        ctx[((size_t)b * 512 + m0 + r) * 512 + i * 64 + c] = vv;
    }
}

// ---------------- launch ----------------------------------------------------
extern "C" void kernel_launch(void* const* d_in, const int* in_sizes, int n_in,
                              void* d_out, int out_size)
{
    const float* X   = (const float*)d_in[0];
    const float* w1  = (const float*)d_in[2];
    const float* b1  = (const float*)d_in[3];
    const float* g1  = (const float*)d_in[4];
    const float* be1 = (const float*)d_in[5];
    const float* m1  = (const float*)d_in[6];
    const float* v1  = (const float*)d_in[7];
    const float* w2  = (const float*)d_in[8];
    const float* b2  = (const float*)d_in[9];
    const float* g2  = (const float*)d_in[10];
    const float* be2 = (const float*)d_in[11];
    const float* m2  = (const float*)d_in[12];
    const float* v2  = (const float*)d_in[13];

    float* out  = (float*)d_out;
    float* attn = out + (size_t)4 * 512 * 512;

    float *mid, *qkv, *ctx;
    cudaGetSymbolAddress((void**)&mid, g_mid);
    cudaGetSymbolAddress((void**)&qkv, g_qkv);
    cudaGetSymbolAddress((void**)&ctx, g_ctx);

    const int SMEM = SMEM_WORDS * 4;  // 216192 B
    cudaFuncSetAttribute(attn_kernel, cudaFuncAttributeMaxDynamicSharedMemorySize, SMEM);

    dim3 cb1(64, 4), cb2(32, 8);

    conv1_kernel<<<dim3(8, 128, 96), cb1>>>(X, w1, b1, g1, be1, m1, v1, mid, 0);
    conv2_kernel<<<dim3(16, 64, 12), cb2>>>(mid, w2, b2, g2, be2, m2, v2, qkv, 0);

    attn_kernel<<<dim3(8, 8, 4), 512, SMEM>>>(qkv, qkv + 1048576, qkv + 2097152, attn, ctx);

    conv1_kernel<<<dim3(8, 128, 32), cb1>>>(ctx, w1, b1, g1, be1, m1, v1, mid, 3);
    conv2_kernel<<<dim3(16, 64, 4), cb2>>>(mid, w2, b2, g2, be2, m2, v2, out, 3);
}